// round 11
// baseline (speedup 1.0000x reference)
#include <cuda_runtime.h>
#include <math.h>
#include <stdint.h>

#define NN     4096
#define BB     2
#define FIN    128
#define FOUT   64
#define NW     128
#define ALPHA  0.2f

#define SPLITS  8
#define KR      (NN/SPLITS)     // 512 k per CTA
#define NT      8               // tiles of 64 k

// k_main smem byte offsets
#define BITSB  8192
#define BSTR   20               // 16 words + pad
#define BBUFB  (BITSB + 128*BSTR*4)        // 18432
#define SMEMB  (BBUFB + 2*1024*16)         // 51200

__device__ float4   g_row[BB*NN];         // (s1, exp(s1), exp(a*s1), -)
__device__ float4   g_c2 [BB*NN];         // (s2, exp(s2), exp(a*s2), -)
__device__ float    g_Zp[SPLITS*BB*NN];
__device__ unsigned g_adjbits[NN*NW];
__device__ uint4    g_WhF4[BB*65536];     // Wh in B-fragment order, tf32-rounded
__device__ float    g_accA[SPLITS*BB*NN*FOUT];   // 16 MB split partials

__device__ __forceinline__ float elu1(float v) { return v > 0.f ? v : expm1f(v); }
__device__ __forceinline__ unsigned tf32r(float x) {
    unsigned u;
    asm("cvt.rna.tf32.f32 %0, %1;" : "=r"(u) : "f"(x));
    return u;
}
__device__ __forceinline__ void mma8(float* c, unsigned a0, unsigned a1,
                                     unsigned a2, unsigned a3,
                                     unsigned b0, unsigned b1) {
    asm volatile("mma.sync.aligned.m16n8k8.row.col.f32.tf32.tf32.f32 "
        "{%0,%1,%2,%3}, {%4,%5,%6,%7}, {%8,%9}, {%0,%1,%2,%3};"
        : "+f"(c[0]), "+f"(c[1]), "+f"(c[2]), "+f"(c[3])
        : "r"(a0), "r"(a1), "r"(a2), "r"(a3), "r"(b0), "r"(b1));
}

// ---------------- K1: Wh (fragment layout) + row/col factors + adj pack ----
__global__ __launch_bounds__(256) void k_proj(const float* __restrict__ h,
                                              const float* __restrict__ W,
                                              const float* __restrict__ a,
                                              const int* __restrict__ adj) {
    __shared__ float  Ws[FIN*FOUT];
    __shared__ float  hS[16*FIN];
    __shared__ float2 sred[8][4];
    int tid = threadIdx.x, lane = tid & 31, wid = tid >> 5;
    {
        const float4* w4 = (const float4*)W;
        float4* d4 = (float4*)Ws;
#pragma unroll
        for (int k = 0; k < 8; k++) d4[tid + k*256] = w4[tid + k*256];
    }
    int rowbase = blockIdx.x * 16;
    {
        const float4* h4s = (const float4*)(h + (size_t)rowbase * FIN);
        float4* d4 = (float4*)hS;
        d4[tid] = h4s[tid]; d4[tid+256] = h4s[tid+256];
    }
    __syncthreads();

    // ---- GEMM: each thread -> 4 rows (r4, r4+4, r4+8, r4+12), col o --------
    int o = tid & 63, r4 = tid >> 6;
    float acc0 = 0.f, acc1 = 0.f, acc2 = 0.f, acc3 = 0.f;
    const float4* h4 = (const float4*)hS;
#pragma unroll
    for (int f4 = 0; f4 < 32; f4++) {
        float w0 = Ws[(f4*4+0)*FOUT + o];
        float w1 = Ws[(f4*4+1)*FOUT + o];
        float w2 = Ws[(f4*4+2)*FOUT + o];
        float w3 = Ws[(f4*4+3)*FOUT + o];
        float4 hv0 = h4[(r4+ 0)*32 + f4];
        float4 hv1 = h4[(r4+ 4)*32 + f4];
        float4 hv2 = h4[(r4+ 8)*32 + f4];
        float4 hv3 = h4[(r4+12)*32 + f4];
        acc0 = fmaf(hv0.x,w0, fmaf(hv0.y,w1, fmaf(hv0.z,w2, fmaf(hv0.w,w3, acc0))));
        acc1 = fmaf(hv1.x,w0, fmaf(hv1.y,w1, fmaf(hv1.z,w2, fmaf(hv1.w,w3, acc1))));
        acc2 = fmaf(hv2.x,w0, fmaf(hv2.y,w1, fmaf(hv2.z,w2, fmaf(hv2.w,w3, acc2))));
        acc3 = fmaf(hv3.x,w0, fmaf(hv3.y,w1, fmaf(hv3.z,w2, fmaf(hv3.w,w3, acc3))));
    }
    float a1v = __ldg(a + o), a2v = __ldg(a + FOUT + o);
    unsigned* whf = (unsigned*)g_WhF4;
    float accs[4] = {acc0, acc1, acc2, acc3};
#pragma unroll
    for (int rr = 0; rr < 4; rr++) {
        float acc = accs[rr];
        int gr = rowbase + r4 + rr*4;
        int bb = gr >> 12, k = gr & (NN-1);
        int f4i = ((k >> 4)*8 + (o >> 3))*32 + ((o & 7)*4 + (k & 3));
        whf[(size_t)bb*262144 + (size_t)f4i*4 + ((k >> 2) & 3)] = tf32r(acc);
        float p1 = acc * a1v, p2 = acc * a2v;
#pragma unroll
        for (int off = 16; off; off >>= 1) {
            p1 += __shfl_xor_sync(0xffffffffu, p1, off);
            p2 += __shfl_xor_sync(0xffffffffu, p2, off);
        }
        if (lane == 0) sred[wid][rr] = make_float2(p1, p2);
    }
    __syncthreads();
    if (tid < 16) {
        int rq = tid & 3, rr = tid >> 2;
        float2 x = sred[2*rq][rr], y = sred[2*rq+1][rr];
        float s1v = x.x + y.x;
        float s2v = x.y + y.y;
        int gi = rowbase + rq + rr*4;
        g_row[gi] = make_float4(s1v, __expf(s1v), __expf(ALPHA*s1v), 0.f);
        g_c2[gi]  = make_float4(s2v, __expf(s2v), __expf(ALPHA*s2v), 0.f);
    }

    // ---- adj pack: lane-owns-word, no shuffles -----------------------------
    {
        int prow = blockIdx.x * 8 + wid;     // grid 512 * 8 = 4096 rows
        const int4* arow4 = (const int4*)(adj + (size_t)prow * NN);
#pragma unroll
        for (int q = 0; q < 4; q++) {
            const int4* p = arow4 + (q*32 + lane)*8;   // lane's own 128B chunk
            int4 v[8];
#pragma unroll
            for (int s = 0; s < 8; s++) v[s] = __ldcs(p + s);
            unsigned w = 0;
#pragma unroll
            for (int s = 0; s < 8; s++) {
                unsigned nib = ((unsigned)v[s].x & 1u) | (((unsigned)v[s].y & 1u) << 1)
                             | (((unsigned)v[s].z & 1u) << 2) | (((unsigned)v[s].w & 1u) << 3);
                w |= nib << (s*4);
            }
            g_adjbits[(size_t)prow * NW + q*32 + lane] = w;
        }
    }
}

// ---------------- K2: mma.sync tf32 GEMM, K-split 8, factorized exp --------
// Grid (32 rowtiles, 8 ksplits, 2 batches). 8 warps x 16 exclusive rows.
__global__ __launch_bounds__(256, 2) void k_main() {
    extern __shared__ char smem[];
    float4*   c2S   = (float4*)smem;                // KR float4 (8 KB)
    unsigned* bitsS = (unsigned*)(smem + BITSB);    // 128 x BSTR
    uint4*    Bbuf  = (uint4*)(smem + BBUFB);       // 2 x 1024 uint4

    int tid = threadIdx.x, lane = tid & 31, wid = tid >> 5;
    int b = blockIdx.z, split = blockIdx.y;
    int i0 = blockIdx.x * 128;
    int kbase = split * KR;

    // stage c2 chunk (KR float4)
    {
        const float4* src = (const float4*)(g_c2 + b*NN + kbase);
        c2S[tid] = src[tid]; c2S[tid + 256] = src[tid + 256];
    }
    // stage bits: 128 rows x 16 words
    {
        int row = tid >> 1, hh = tid & 1;
        const uint4* src = (const uint4*)(g_adjbits + (size_t)(i0+row)*NW + (kbase >> 5) + hh*8);
        uint4* dst = (uint4*)(bitsS + row*BSTR + hh*8);
        dst[0] = src[0]; dst[1] = src[1];
    }
    const uint4* srcB = g_WhF4 + (size_t)b * 65536;
    // preload tile 0
    {
        const uint4* s = srcB + (size_t)(kbase >> 4) * 256;
#pragma unroll
        for (int j = 0; j < 4; j++) Bbuf[tid + j*256] = __ldg(s + tid + j*256);
    }
    int r0l = wid*16 + (lane >> 2);
    float4 rv0 = g_row[b*NN + i0 + r0l];       // (s1, E1, E1p, -)
    float4 rv1 = g_row[b*NN + i0 + r0l + 8];
    const unsigned* bw0 = bitsS + r0l * BSTR;
    const unsigned* bw1 = bitsS + (r0l + 8) * BSTR;
    __syncthreads();

    float acc[8][4];
#pragma unroll
    for (int nt = 0; nt < 8; nt++)
#pragma unroll
        for (int c = 0; c < 4; c++) acc[nt][c] = 0.f;
    float z0 = 0.f, z1 = 0.f;

    for (int t = 0; t < NT; t++) {
        int cur = t & 1;
        uint4 st0, st1, st2, st3;
        if (t + 1 < NT) {
            const uint4* s = srcB + (size_t)((kbase >> 4) + (t+1)*4) * 256;
            st0 = __ldg(s + tid);       st1 = __ldg(s + tid + 256);
            st2 = __ldg(s + tid + 512); st3 = __ldg(s + tid + 768);
        }
        const uint4* bb4 = Bbuf + cur*1024;
        unsigned w0  = bw0[2*t], w0b = bw0[2*t + 1];
        unsigned w1  = bw1[2*t], w1b = bw1[2*t + 1];
        uint4 bq[8];
#pragma unroll
        for (int kk = 0; kk < 8; kk++) {
            int kl = t*64 + kk*8 + (lane & 3);
            float4 ca = c2S[kl];          // (s2, E2, E2p, -)
            float4 cb = c2S[kl + 4];
            unsigned wa = (kk < 4) ? w0 : w0b;
            unsigned wb = (kk < 4) ? w1 : w1b;
            int pos = ((kk & 3) << 3) + (lane & 3);
            unsigned ta = wa >> pos, tb = wb >> pos;
            float e0 = rv0.x + ca.x;
            float e1 = rv1.x + ca.x;
            float e2 = rv0.x + cb.x;
            float e3 = rv1.x + cb.x;
            float p0 = (ta & 1u)        ? (e0 >= 0.f ? rv0.y*ca.y : rv0.z*ca.z) : 0.f;
            float p1 = (tb & 1u)        ? (e1 >= 0.f ? rv1.y*ca.y : rv1.z*ca.z) : 0.f;
            float p2 = ((ta >> 4) & 1u) ? (e2 >= 0.f ? rv0.y*cb.y : rv0.z*cb.z) : 0.f;
            float p3 = ((tb >> 4) & 1u) ? (e3 >= 0.f ? rv1.y*cb.y : rv1.z*cb.z) : 0.f;
            z0 += p0 + p2;
            z1 += p1 + p3;
            unsigned a0 = tf32r(p0), a1 = tf32r(p1), a2 = tf32r(p2), a3 = tf32r(p3);
            if ((kk & 1) == 0) {
#pragma unroll
                for (int nt = 0; nt < 8; nt++)
                    bq[nt] = bb4[(kk >> 1)*256 + nt*32 + lane];
            }
#pragma unroll
            for (int nt = 0; nt < 8; nt++) {
                unsigned bx = (kk & 1) ? bq[nt].z : bq[nt].x;
                unsigned by = (kk & 1) ? bq[nt].w : bq[nt].y;
                mma8(acc[nt], a0, a1, a2, a3, bx, by);
            }
        }
        if (t + 1 < NT) {
            uint4* d = Bbuf + (cur^1)*1024;
            d[tid] = st0; d[tid+256] = st1; d[tid+512] = st2; d[tid+768] = st3;
        }
        __syncthreads();
    }

    // Z partials: reduce over the 4 lanes of each quad (deterministic)
    z0 += __shfl_xor_sync(0xffffffffu, z0, 1);
    z0 += __shfl_xor_sync(0xffffffffu, z0, 2);
    z1 += __shfl_xor_sync(0xffffffffu, z1, 1);
    z1 += __shfl_xor_sync(0xffffffffu, z1, 2);
    if ((lane & 3) == 0) {
        g_Zp[split*BB*NN + b*NN + i0 + r0l]     = z0;
        g_Zp[split*BB*NN + b*NN + i0 + r0l + 8] = z1;
    }

    // write split partials
    float* accp = g_accA + (size_t)split*BB*NN*FOUT
                  + ((size_t)(b*NN + i0 + r0l)) * FOUT;
#pragma unroll
    for (int nt = 0; nt < 8; nt++) {
        int col = nt*8 + 2*(lane & 3);
        *(float2*)(accp + col)            = make_float2(acc[nt][0], acc[nt][1]);
        *(float2*)(accp + 8*FOUT + col)   = make_float2(acc[nt][2], acc[nt][3]);
    }
}

// ---------------- K3: combine splits, normalize, ELU -----------------------
__global__ void k_final(float* __restrict__ out) {
    int idx = blockIdx.x * 256 + threadIdx.x;
    int row = idx >> 4;
    float4 v = make_float4(0.f, 0.f, 0.f, 0.f);
    float Z = 0.f;
#pragma unroll
    for (int s = 0; s < SPLITS; s++) {
        float4 t = ((const float4*)(g_accA + (size_t)s*BB*NN*FOUT))[idx];
        v.x += t.x; v.y += t.y; v.z += t.z; v.w += t.w;
        Z += g_Zp[s*BB*NN + row];
    }
    float inv = 1.f / Z;
    float4 o;
    o.x = elu1(v.x * inv);
    o.y = elu1(v.y * inv);
    o.z = elu1(v.z * inv);
    o.w = elu1(v.w * inv);
    ((float4*)out)[idx] = o;
}

// ---------------- launch ---------------------------------------------------
extern "C" void kernel_launch(void* const* d_in, const int* in_sizes, int n_in,
                              void* d_out, int out_size) {
    const float* h   = (const float*)d_in[0];
    const int*   adj = (const int*)  d_in[1];
    const float* W   = (const float*)d_in[2];
    const float* a   = (const float*)d_in[3];
    float* out = (float*)d_out;

    cudaFuncSetAttribute(k_main, cudaFuncAttributeMaxDynamicSharedMemorySize, SMEMB);

    k_proj <<<(BB*NN)/16, 256>>>(h, W, a, adj);
    k_main <<<dim3(NN/128, SPLITS, BB), 256, SMEMB>>>();
    k_final<<<(BB*NN*FOUT)/(4*256), 256>>>(out);
}

// round 13
// speedup vs baseline: 2.4167x; 2.4167x over previous
#include <cuda_runtime.h>
#include <math.h>
#include <stdint.h>

#define NN     4096
#define BB     2
#define FIN    128
#define FOUT   64
#define NW     128
#define ALPHA  0.2f
#define LOG2E  1.4426950408889634f

#define SPLITS  8
#define KR      (NN/SPLITS)     // 512 k per CTA
#define NT      8               // tiles of 64 k

// k_main smem byte offsets
#define BITSB  2048
#define BSTR   20               // 16 words + pad
#define BBUFB  (BITSB + 128*BSTR*4)        // 12288
#define SMEMB  (BBUFB + 2*8192)            // 28672 (2 x 8KB B buffers)

__device__ float    g_s1[BB*NN];          // prescaled by log2(e)
__device__ float    g_s2[BB*NN];          // prescaled by log2(e)
__device__ float    g_Zp[SPLITS*BB*NN];
__device__ unsigned g_adjbits[NN*NW];
__device__ uint2    g_WhB[BB*65536];      // Wh bf16, B-fragment order (1 MB)
__device__ float    g_accA[SPLITS*BB*NN*FOUT];

__device__ __forceinline__ float elu1(float v) { return v > 0.f ? v : expm1f(v); }
__device__ __forceinline__ unsigned short b16(float x) {
    unsigned short u;
    asm("cvt.rn.bf16.f32 %0, %1;" : "=h"(u) : "f"(x));
    return u;
}
__device__ __forceinline__ unsigned bf2(float lo, float hi) {
    unsigned r;
    asm("cvt.rn.bf16x2.f32 %0, %1, %2;" : "=r"(r) : "f"(hi), "f"(lo));
    return r;
}
__device__ __forceinline__ void mma16(float* c, unsigned a0, unsigned a1,
                                      unsigned a2, unsigned a3,
                                      unsigned b0, unsigned b1) {
    asm volatile("mma.sync.aligned.m16n8k16.row.col.f32.bf16.bf16.f32 "
        "{%0,%1,%2,%3}, {%4,%5,%6,%7}, {%8,%9}, {%0,%1,%2,%3};"
        : "+f"(c[0]), "+f"(c[1]), "+f"(c[2]), "+f"(c[3])
        : "r"(a0), "r"(a1), "r"(a2), "r"(a3), "r"(b0), "r"(b1));
}
// e2 is prescaled by log2(e): p = 2^max(e2, alpha*e2), masked
__device__ __forceinline__ float pexp2(float e2, unsigned bit) {
    float l = fmaxf(e2, ALPHA * e2);
    float p;
    asm("ex2.approx.f32 %0, %1;" : "=f"(p) : "f"(l));
    return bit ? p : 0.f;
}

// ---------------- K1: Wh (bf16 fragment layout) + s1 + s2 + adj pack -------
__global__ __launch_bounds__(256) void k_proj(const float* __restrict__ h,
                                              const float* __restrict__ W,
                                              const float* __restrict__ a,
                                              const int* __restrict__ adj) {
    __shared__ float  Ws[FIN*FOUT];
    __shared__ float  hS[16*FIN];
    __shared__ float2 sred[8][4];
    int tid = threadIdx.x, lane = tid & 31, wid = tid >> 5;
    {
        const float4* w4 = (const float4*)W;
        float4* d4 = (float4*)Ws;
#pragma unroll
        for (int k = 0; k < 8; k++) d4[tid + k*256] = w4[tid + k*256];
    }
    int rowbase = blockIdx.x * 16;
    {
        const float4* h4s = (const float4*)(h + (size_t)rowbase * FIN);
        float4* d4 = (float4*)hS;
        d4[tid] = h4s[tid]; d4[tid+256] = h4s[tid+256];
    }
    __syncthreads();

    int o = tid & 63, r4 = tid >> 6;
    float acc0 = 0.f, acc1 = 0.f, acc2 = 0.f, acc3 = 0.f;
    const float4* h4 = (const float4*)hS;
#pragma unroll
    for (int f4 = 0; f4 < 32; f4++) {
        float w0 = Ws[(f4*4+0)*FOUT + o];
        float w1 = Ws[(f4*4+1)*FOUT + o];
        float w2 = Ws[(f4*4+2)*FOUT + o];
        float w3 = Ws[(f4*4+3)*FOUT + o];
        float4 hv0 = h4[(r4+ 0)*32 + f4];
        float4 hv1 = h4[(r4+ 4)*32 + f4];
        float4 hv2 = h4[(r4+ 8)*32 + f4];
        float4 hv3 = h4[(r4+12)*32 + f4];
        acc0 = fmaf(hv0.x,w0, fmaf(hv0.y,w1, fmaf(hv0.z,w2, fmaf(hv0.w,w3, acc0))));
        acc1 = fmaf(hv1.x,w0, fmaf(hv1.y,w1, fmaf(hv1.z,w2, fmaf(hv1.w,w3, acc1))));
        acc2 = fmaf(hv2.x,w0, fmaf(hv2.y,w1, fmaf(hv2.z,w2, fmaf(hv2.w,w3, acc2))));
        acc3 = fmaf(hv3.x,w0, fmaf(hv3.y,w1, fmaf(hv3.z,w2, fmaf(hv3.w,w3, acc3))));
    }
    float a1v = __ldg(a + o), a2v = __ldg(a + FOUT + o);
    unsigned short* whb = (unsigned short*)g_WhB;
    float accs[4] = {acc0, acc1, acc2, acc3};
#pragma unroll
    for (int rr = 0; rr < 4; rr++) {
        float acc = accs[rr];
        int gr = rowbase + r4 + rr*4;
        int bb = gr >> 12, k = gr & (NN-1);
        // bf16 B-fragment scatter for m16n8k16: chunk kc=k/16, ntile=o/8,
        // lane = (o%8)*4 + ((k%16)/2)%4, reg = (k%16)/8, half = k%2
        int kc = k >> 4, kl = k & 15;
        size_t idx = ((((size_t)bb*256 + kc)*8 + (o >> 3))*32
                      + (o & 7)*4 + ((kl >> 1) & 3))*4 + ((kl >> 3) << 1) + (kl & 1);
        whb[idx] = b16(acc);
        float p1 = acc * a1v, p2 = acc * a2v;
#pragma unroll
        for (int off = 16; off; off >>= 1) {
            p1 += __shfl_xor_sync(0xffffffffu, p1, off);
            p2 += __shfl_xor_sync(0xffffffffu, p2, off);
        }
        if (lane == 0) sred[wid][rr] = make_float2(p1, p2);
    }
    __syncthreads();
    if (tid < 16) {
        int rq = tid & 3, rr = tid >> 2;
        float2 x = sred[2*rq][rr], y = sred[2*rq+1][rr];
        g_s1[rowbase + rq + rr*4] = (x.x + y.x) * LOG2E;
        g_s2[rowbase + rq + rr*4] = (x.y + y.y) * LOG2E;
    }

    // ---- adj pack: warp-per-row, int4 coalesced loads + shuffle bit-merge --
    {
        int prow = blockIdx.x * 8 + wid;
        const int4* arow4 = (const int4*)(adj + (size_t)prow * NN);
        int src = (lane & 3) * 8;
#pragma unroll
        for (int q = 0; q < 4; q++) {
            int4 v[8];
#pragma unroll
            for (int s = 0; s < 8; s++)
                v[s] = __ldcs(arow4 + q*256 + s*32 + lane);
            unsigned myw = 0;
#pragma unroll
            for (int s = 0; s < 8; s++) {
                unsigned nib = ((unsigned)v[s].x & 1u) | (((unsigned)v[s].y & 1u) << 1)
                             | (((unsigned)v[s].z & 1u) << 2) | (((unsigned)v[s].w & 1u) << 3);
                unsigned t;
                t = __shfl_xor_sync(0xffffffffu, nib, 1);
                nib = (lane & 1) ? (t | (nib << 4))  : (nib | (t << 4));
                t = __shfl_xor_sync(0xffffffffu, nib, 2);
                nib = (lane & 2) ? (t | (nib << 8))  : (nib | (t << 8));
                t = __shfl_xor_sync(0xffffffffu, nib, 4);
                nib = (lane & 4) ? (t | (nib << 16)) : (nib | (t << 16));
                unsigned w = __shfl_sync(0xffffffffu, nib, src);
                if ((lane >> 2) == s) myw = w;
            }
            g_adjbits[(size_t)prow * NW + q*32 + lane] = myw;
        }
    }
}

// ---------------- K2: mma.sync bf16 GEMM, K-split 8, fused Z ---------------
// Grid (32 rowtiles, 8 ksplits, 2 batches). 8 warps x 16 exclusive rows.
__global__ __launch_bounds__(256, 2) void k_main() {
    extern __shared__ char smem[];
    float*    s2S   = (float*)smem;                 // KR floats (2 KB)
    unsigned* bitsS = (unsigned*)(smem + BITSB);    // 128 x BSTR
    uint2*    Bbuf2 = (uint2*)(smem + BBUFB);       // 2 x 1024 uint2 (8KB each)

    int tid = threadIdx.x, lane = tid & 31, wid = tid >> 5;
    int b = blockIdx.z, split = blockIdx.y;
    int i0 = blockIdx.x * 128;
    int kbase = split * KR;
    int kc0 = split * 32;                           // first 16-k chunk index

    if (tid < KR/4)
        ((float4*)s2S)[tid] = ((const float4*)(g_s2 + b*NN + kbase))[tid];
    {
        int row = tid >> 1, hh = tid & 1;
        const uint4* src = (const uint4*)(g_adjbits + (size_t)(i0+row)*NW + (kbase >> 5) + hh*8);
        uint4* dst = (uint4*)(bitsS + row*BSTR + hh*8);
        dst[0] = src[0]; dst[1] = src[1];
    }
    const uint4* sB = ((const uint4*)g_WhB) + (size_t)b * 32768;
    // preload tile 0 (8 KB = 512 uint4)
    {
        const uint4* s = sB + (size_t)kc0 * 128;
        uint4* d = (uint4*)(smem + BBUFB);
        d[tid] = __ldg(s + tid); d[tid + 256] = __ldg(s + tid + 256);
    }
    int r0l = wid*16 + (lane >> 2);
    int c = lane & 3;
    float s1r0 = g_s1[b*NN + i0 + r0l];
    float s1r1 = g_s1[b*NN + i0 + r0l + 8];
    const unsigned* bw0 = bitsS + r0l * BSTR;
    const unsigned* bw1 = bitsS + (r0l + 8) * BSTR;
    const float2* s2f2 = (const float2*)s2S;
    __syncthreads();

    float acc[8][4];
#pragma unroll
    for (int nt = 0; nt < 8; nt++)
#pragma unroll
        for (int cc = 0; cc < 4; cc++) acc[nt][cc] = 0.f;
    float z0 = 0.f, z1 = 0.f;

    for (int t = 0; t < NT; t++) {
        int cur = t & 1;
        uint4 st0, st1;
        if (t + 1 < NT) {
            const uint4* s = sB + (size_t)(kc0 + (t+1)*4) * 128;
            st0 = __ldg(s + tid); st1 = __ldg(s + tid + 256);
        }
        unsigned w0  = bw0[2*t], w0b = bw0[2*t + 1];
        unsigned w1  = bw1[2*t], w1b = bw1[2*t + 1];
#pragma unroll
        for (int cc = 0; cc < 4; cc++) {
            float2 sa = s2f2[t*32 + cc*8 + c];
            float2 sb = s2f2[t*32 + cc*8 + 4 + c];
            unsigned sel0 = (cc & 2) ? w0b : w0;
            unsigned sel1 = (cc & 2) ? w1b : w1;
            int sh = ((cc & 1) << 4) + (c << 1);
            unsigned t0 = sel0 >> sh, t1 = sel1 >> sh;
            float p00 = pexp2(s1r0 + sa.x, t0 & 1u);
            float p01 = pexp2(s1r0 + sa.y, (t0 >> 1) & 1u);
            float p08 = pexp2(s1r0 + sb.x, (t0 >> 8) & 1u);
            float p09 = pexp2(s1r0 + sb.y, (t0 >> 9) & 1u);
            float p10 = pexp2(s1r1 + sa.x, t1 & 1u);
            float p11 = pexp2(s1r1 + sa.y, (t1 >> 1) & 1u);
            float p18 = pexp2(s1r1 + sb.x, (t1 >> 8) & 1u);
            float p19 = pexp2(s1r1 + sb.y, (t1 >> 9) & 1u);
            z0 += (p00 + p01) + (p08 + p09);
            z1 += (p10 + p11) + (p18 + p19);
            unsigned a0 = bf2(p00, p01);
            unsigned a1 = bf2(p10, p11);
            unsigned a2 = bf2(p08, p09);
            unsigned a3 = bf2(p18, p19);
            const uint2* bb2 = Bbuf2 + cur*1024 + cc*256;
#pragma unroll
            for (int nt = 0; nt < 8; nt++) {
                uint2 bv = bb2[nt*32 + lane];
                mma16(acc[nt], a0, a1, a2, a3, bv.x, bv.y);
            }
        }
        if (t + 1 < NT) {
            uint4* d = (uint4*)(smem + BBUFB) + (cur^1)*512;
            d[tid] = st0; d[tid + 256] = st1;
        }
        __syncthreads();
    }

    z0 += __shfl_xor_sync(0xffffffffu, z0, 1);
    z0 += __shfl_xor_sync(0xffffffffu, z0, 2);
    z1 += __shfl_xor_sync(0xffffffffu, z1, 1);
    z1 += __shfl_xor_sync(0xffffffffu, z1, 2);
    if ((lane & 3) == 0) {
        g_Zp[split*BB*NN + b*NN + i0 + r0l]     = z0;
        g_Zp[split*BB*NN + b*NN + i0 + r0l + 8] = z1;
    }

    float* accp = g_accA + (size_t)split*BB*NN*FOUT
                  + ((size_t)(b*NN + i0 + r0l)) * FOUT;
#pragma unroll
    for (int nt = 0; nt < 8; nt++) {
        int col = nt*8 + 2*(lane & 3);
        *(float2*)(accp + col)            = make_float2(acc[nt][0], acc[nt][1]);
        *(float2*)(accp + 8*FOUT + col)   = make_float2(acc[nt][2], acc[nt][3]);
    }
}

// ---------------- K3: combine splits, normalize, ELU -----------------------
__global__ void k_final(float* __restrict__ out) {
    int idx = blockIdx.x * 256 + threadIdx.x;
    int row = idx >> 4;
    float4 v = make_float4(0.f, 0.f, 0.f, 0.f);
    float Z = 0.f;
#pragma unroll
    for (int s = 0; s < SPLITS; s++) {
        float4 t = ((const float4*)(g_accA + (size_t)s*BB*NN*FOUT))[idx];
        v.x += t.x; v.y += t.y; v.z += t.z; v.w += t.w;
        Z += g_Zp[s*BB*NN + row];
    }
    float inv = 1.f / Z;
    float4 o;
    o.x = elu1(v.x * inv);
    o.y = elu1(v.y * inv);
    o.z = elu1(v.z * inv);
    o.w = elu1(v.w * inv);
    ((float4*)out)[idx] = o;
}

// ---------------- launch ---------------------------------------------------
extern "C" void kernel_launch(void* const* d_in, const int* in_sizes, int n_in,
                              void* d_out, int out_size) {
    const float* h   = (const float*)d_in[0];
    const int*   adj = (const int*)  d_in[1];
    const float* W   = (const float*)d_in[2];
    const float* a   = (const float*)d_in[3];
    float* out = (float*)d_out;

    cudaFuncSetAttribute(k_main, cudaFuncAttributeMaxDynamicSharedMemorySize, SMEMB);

    k_proj <<<(BB*NN)/16, 256>>>(h, W, a, adj);
    k_main <<<dim3(NN/128, SPLITS, BB), 256, SMEMB>>>();
    k_final<<<(BB*NN*FOUT)/(4*256), 256>>>(out);
}

// round 14
// speedup vs baseline: 2.5050x; 1.0365x over previous
#include <cuda_runtime.h>
#include <math.h>
#include <stdint.h>

#define NN     4096
#define BB     2
#define FIN    128
#define FOUT   64
#define NW     128
#define ALPHA  0.2f
#define LOG2E  1.4426950408889634f

#define SPLITS  8
#define KR      (NN/SPLITS)     // 512 k per CTA
#define NT      8               // tiles of 64 k

// k_main smem byte offsets
#define BITSB  2048
#define BSTR   20               // 16 words + pad
#define BBUFB  (BITSB + 128*BSTR*4)        // 12288
#define SMEMB  (BBUFB + 2*8192)            // 28672 (2 x 8KB B buffers)

__device__ float    g_s1[BB*NN];          // prescaled by log2(e)
__device__ float    g_s2[BB*NN];          // prescaled by log2(e)
__device__ float    g_Zp[SPLITS*BB*NN];
__device__ unsigned g_adjbits[NN*NW];
__device__ uint2    g_WhB[BB*65536];      // Wh bf16, B-fragment order (1 MB)
__device__ float    g_accA[SPLITS*BB*NN*FOUT];

__device__ __forceinline__ float elu1(float v) { return v > 0.f ? v : expm1f(v); }
__device__ __forceinline__ unsigned short b16(float x) {
    unsigned short u;
    asm("cvt.rn.bf16.f32 %0, %1;" : "=h"(u) : "f"(x));
    return u;
}
__device__ __forceinline__ unsigned bf2(float lo, float hi) {
    unsigned r;
    asm("cvt.rn.bf16x2.f32 %0, %1, %2;" : "=r"(r) : "f"(hi), "f"(lo));
    return r;
}
__device__ __forceinline__ void mma16(float* c, unsigned a0, unsigned a1,
                                      unsigned a2, unsigned a3,
                                      unsigned b0, unsigned b1) {
    asm volatile("mma.sync.aligned.m16n8k16.row.col.f32.bf16.bf16.f32 "
        "{%0,%1,%2,%3}, {%4,%5,%6,%7}, {%8,%9}, {%0,%1,%2,%3};"
        : "+f"(c[0]), "+f"(c[1]), "+f"(c[2]), "+f"(c[3])
        : "r"(a0), "r"(a1), "r"(a2), "r"(a3), "r"(b0), "r"(b1));
}
// e2 is prescaled by log2(e): p = 2^max(e2, alpha*e2), masked
__device__ __forceinline__ float pexp2(float e2, unsigned bit) {
    float l = fmaxf(e2, ALPHA * e2);
    float p;
    asm("ex2.approx.f32 %0, %1;" : "=f"(p) : "f"(l));
    return bit ? p : 0.f;
}

// ---------------- K1: heterogeneous — GEMM CTAs (0..511) + pack CTAs -------
__global__ __launch_bounds__(256) void k_proj(const float* __restrict__ h,
                                              const float* __restrict__ W,
                                              const float* __restrict__ a,
                                              const int* __restrict__ adj) {
    __shared__ float  Ws[FIN*FOUT];
    __shared__ float  hS[16*FIN];
    __shared__ float2 sred[8][4];
    int tid = threadIdx.x, lane = tid & 31, wid = tid >> 5;

    if (blockIdx.x >= 512) {
        // ---- pack path: 8 rows per CTA, warp-per-row, shuffle bit-merge ----
        int prow = (blockIdx.x - 512) * 8 + wid;
        const int4* arow4 = (const int4*)(adj + (size_t)prow * NN);
        int src = (lane & 3) * 8;
#pragma unroll
        for (int q = 0; q < 4; q++) {
            int4 v[8];
#pragma unroll
            for (int s = 0; s < 8; s++)
                v[s] = __ldcs(arow4 + q*256 + s*32 + lane);
            unsigned myw = 0;
#pragma unroll
            for (int s = 0; s < 8; s++) {
                unsigned nib = ((unsigned)v[s].x & 1u) | (((unsigned)v[s].y & 1u) << 1)
                             | (((unsigned)v[s].z & 1u) << 2) | (((unsigned)v[s].w & 1u) << 3);
                unsigned t;
                t = __shfl_xor_sync(0xffffffffu, nib, 1);
                nib = (lane & 1) ? (t | (nib << 4))  : (nib | (t << 4));
                t = __shfl_xor_sync(0xffffffffu, nib, 2);
                nib = (lane & 2) ? (t | (nib << 8))  : (nib | (t << 8));
                t = __shfl_xor_sync(0xffffffffu, nib, 4);
                nib = (lane & 4) ? (t | (nib << 16)) : (nib | (t << 16));
                unsigned w = __shfl_sync(0xffffffffu, nib, src);
                if ((lane >> 2) == s) myw = w;
            }
            g_adjbits[(size_t)prow * NW + q*32 + lane] = myw;
        }
        return;
    }

    // ---- GEMM path: Wh (bf16 fragment layout) + s1 + s2 --------------------
    {
        const float4* w4 = (const float4*)W;
        float4* d4 = (float4*)Ws;
#pragma unroll
        for (int k = 0; k < 8; k++) d4[tid + k*256] = w4[tid + k*256];
    }
    int rowbase = blockIdx.x * 16;
    {
        const float4* h4s = (const float4*)(h + (size_t)rowbase * FIN);
        float4* d4 = (float4*)hS;
        d4[tid] = h4s[tid]; d4[tid+256] = h4s[tid+256];
    }
    __syncthreads();

    int o = tid & 63, r4 = tid >> 6;
    float acc0 = 0.f, acc1 = 0.f, acc2 = 0.f, acc3 = 0.f;
    const float4* h4 = (const float4*)hS;
#pragma unroll
    for (int f4 = 0; f4 < 32; f4++) {
        float w0 = Ws[(f4*4+0)*FOUT + o];
        float w1 = Ws[(f4*4+1)*FOUT + o];
        float w2 = Ws[(f4*4+2)*FOUT + o];
        float w3 = Ws[(f4*4+3)*FOUT + o];
        float4 hv0 = h4[(r4+ 0)*32 + f4];
        float4 hv1 = h4[(r4+ 4)*32 + f4];
        float4 hv2 = h4[(r4+ 8)*32 + f4];
        float4 hv3 = h4[(r4+12)*32 + f4];
        acc0 = fmaf(hv0.x,w0, fmaf(hv0.y,w1, fmaf(hv0.z,w2, fmaf(hv0.w,w3, acc0))));
        acc1 = fmaf(hv1.x,w0, fmaf(hv1.y,w1, fmaf(hv1.z,w2, fmaf(hv1.w,w3, acc1))));
        acc2 = fmaf(hv2.x,w0, fmaf(hv2.y,w1, fmaf(hv2.z,w2, fmaf(hv2.w,w3, acc2))));
        acc3 = fmaf(hv3.x,w0, fmaf(hv3.y,w1, fmaf(hv3.z,w2, fmaf(hv3.w,w3, acc3))));
    }
    float a1v = __ldg(a + o), a2v = __ldg(a + FOUT + o);
    unsigned short* whb = (unsigned short*)g_WhB;
    float accs[4] = {acc0, acc1, acc2, acc3};
#pragma unroll
    for (int rr = 0; rr < 4; rr++) {
        float acc = accs[rr];
        int gr = rowbase + r4 + rr*4;
        int bb = gr >> 12, k = gr & (NN-1);
        int kc = k >> 4, kl = k & 15;
        size_t idx = ((((size_t)bb*256 + kc)*8 + (o >> 3))*32
                      + (o & 7)*4 + ((kl >> 1) & 3))*4 + ((kl >> 3) << 1) + (kl & 1);
        whb[idx] = b16(acc);
        float p1 = acc * a1v, p2 = acc * a2v;
#pragma unroll
        for (int off = 16; off; off >>= 1) {
            p1 += __shfl_xor_sync(0xffffffffu, p1, off);
            p2 += __shfl_xor_sync(0xffffffffu, p2, off);
        }
        if (lane == 0) sred[wid][rr] = make_float2(p1, p2);
    }
    __syncthreads();
    if (tid < 16) {
        int rq = tid & 3, rr = tid >> 2;
        float2 x = sred[2*rq][rr], y = sred[2*rq+1][rr];
        g_s1[rowbase + rq + rr*4] = (x.x + y.x) * LOG2E;
        g_s2[rowbase + rq + rr*4] = (x.y + y.y) * LOG2E;
    }
}

// ---------------- K2: mma.sync bf16 GEMM, K-split 8, fused Z ---------------
// Grid (32 rowtiles, 8 ksplits, 2 batches). 8 warps x 16 exclusive rows.
__global__ __launch_bounds__(256, 2) void k_main() {
    extern __shared__ char smem[];
    float*    s2S   = (float*)smem;                 // KR floats (2 KB)
    unsigned* bitsS = (unsigned*)(smem + BITSB);    // 128 x BSTR
    uint2*    Bbuf2 = (uint2*)(smem + BBUFB);       // 2 x 1024 uint2 (8KB each)

    int tid = threadIdx.x, lane = tid & 31, wid = tid >> 5;
    int b = blockIdx.z, split = blockIdx.y;
    int i0 = blockIdx.x * 128;
    int kbase = split * KR;
    int kc0 = split * 32;                           // first 16-k chunk index

    if (tid < KR/4)
        ((float4*)s2S)[tid] = ((const float4*)(g_s2 + b*NN + kbase))[tid];
    {
        int row = tid >> 1, hh = tid & 1;
        const uint4* src = (const uint4*)(g_adjbits + (size_t)(i0+row)*NW + (kbase >> 5) + hh*8);
        uint4* dst = (uint4*)(bitsS + row*BSTR + hh*8);
        dst[0] = src[0]; dst[1] = src[1];
    }
    const uint4* sB = ((const uint4*)g_WhB) + (size_t)b * 32768;
    // preload tile 0 (8 KB = 512 uint4)
    {
        const uint4* s = sB + (size_t)kc0 * 128;
        uint4* d = (uint4*)(smem + BBUFB);
        d[tid] = __ldg(s + tid); d[tid + 256] = __ldg(s + tid + 256);
    }
    int r0l = wid*16 + (lane >> 2);
    int c = lane & 3;
    float s1r0 = g_s1[b*NN + i0 + r0l];
    float s1r1 = g_s1[b*NN + i0 + r0l + 8];
    const unsigned* bw0 = bitsS + r0l * BSTR;
    const unsigned* bw1 = bitsS + (r0l + 8) * BSTR;
    const float2* s2f2 = (const float2*)s2S;
    __syncthreads();

    float acc[8][4];
#pragma unroll
    for (int nt = 0; nt < 8; nt++)
#pragma unroll
        for (int cc = 0; cc < 4; cc++) acc[nt][cc] = 0.f;
    float z0 = 0.f, z1 = 0.f;

    for (int t = 0; t < NT; t++) {
        int cur = t & 1;
        uint4 st0, st1;
        if (t + 1 < NT) {
            const uint4* s = sB + (size_t)(kc0 + (t+1)*4) * 128;
            st0 = __ldg(s + tid); st1 = __ldg(s + tid + 256);
        }
        unsigned w0  = bw0[2*t], w0b = bw0[2*t + 1];
        unsigned w1  = bw1[2*t], w1b = bw1[2*t + 1];
#pragma unroll
        for (int cc = 0; cc < 4; cc++) {
            float2 sa = s2f2[t*32 + cc*8 + c];
            float2 sb = s2f2[t*32 + cc*8 + 4 + c];
            unsigned sel0 = (cc & 2) ? w0b : w0;
            unsigned sel1 = (cc & 2) ? w1b : w1;
            int sh = ((cc & 1) << 4) + (c << 1);
            unsigned t0 = sel0 >> sh, t1 = sel1 >> sh;
            float p00 = pexp2(s1r0 + sa.x, t0 & 1u);
            float p01 = pexp2(s1r0 + sa.y, (t0 >> 1) & 1u);
            float p08 = pexp2(s1r0 + sb.x, (t0 >> 8) & 1u);
            float p09 = pexp2(s1r0 + sb.y, (t0 >> 9) & 1u);
            float p10 = pexp2(s1r1 + sa.x, t1 & 1u);
            float p11 = pexp2(s1r1 + sa.y, (t1 >> 1) & 1u);
            float p18 = pexp2(s1r1 + sb.x, (t1 >> 8) & 1u);
            float p19 = pexp2(s1r1 + sb.y, (t1 >> 9) & 1u);
            z0 += (p00 + p01) + (p08 + p09);
            z1 += (p10 + p11) + (p18 + p19);
            unsigned a0 = bf2(p00, p01);
            unsigned a1 = bf2(p10, p11);
            unsigned a2 = bf2(p08, p09);
            unsigned a3 = bf2(p18, p19);
            const uint2* bb2 = Bbuf2 + cur*1024 + cc*256;
#pragma unroll
            for (int nt = 0; nt < 8; nt++) {
                uint2 bv = bb2[nt*32 + lane];
                mma16(acc[nt], a0, a1, a2, a3, bv.x, bv.y);
            }
        }
        if (t + 1 < NT) {
            uint4* d = (uint4*)(smem + BBUFB) + (cur^1)*512;
            d[tid] = st0; d[tid + 256] = st1;
        }
        __syncthreads();
    }

    z0 += __shfl_xor_sync(0xffffffffu, z0, 1);
    z0 += __shfl_xor_sync(0xffffffffu, z0, 2);
    z1 += __shfl_xor_sync(0xffffffffu, z1, 1);
    z1 += __shfl_xor_sync(0xffffffffu, z1, 2);
    if ((lane & 3) == 0) {
        g_Zp[split*BB*NN + b*NN + i0 + r0l]     = z0;
        g_Zp[split*BB*NN + b*NN + i0 + r0l + 8] = z1;
    }

    float* accp = g_accA + (size_t)split*BB*NN*FOUT
                  + ((size_t)(b*NN + i0 + r0l)) * FOUT;
#pragma unroll
    for (int nt = 0; nt < 8; nt++) {
        int col = nt*8 + 2*(lane & 3);
        *(float2*)(accp + col)            = make_float2(acc[nt][0], acc[nt][1]);
        *(float2*)(accp + 8*FOUT + col)   = make_float2(acc[nt][2], acc[nt][3]);
    }
}

// ---------------- K3: combine splits, normalize, ELU -----------------------
__global__ void k_final(float* __restrict__ out) {
    int idx = blockIdx.x * 256 + threadIdx.x;
    int row = idx >> 4;
    float4 v = make_float4(0.f, 0.f, 0.f, 0.f);
    float Z = 0.f;
#pragma unroll
    for (int s = 0; s < SPLITS; s++) {
        float4 t = ((const float4*)(g_accA + (size_t)s*BB*NN*FOUT))[idx];
        v.x += t.x; v.y += t.y; v.z += t.z; v.w += t.w;
        Z += g_Zp[s*BB*NN + row];
    }
    float inv = 1.f / Z;
    float4 o;
    o.x = elu1(v.x * inv);
    o.y = elu1(v.y * inv);
    o.z = elu1(v.z * inv);
    o.w = elu1(v.w * inv);
    ((float4*)out)[idx] = o;
}

// ---------------- launch ---------------------------------------------------
extern "C" void kernel_launch(void* const* d_in, const int* in_sizes, int n_in,
                              void* d_out, int out_size) {
    const float* h   = (const float*)d_in[0];
    const int*   adj = (const int*)  d_in[1];
    const float* W   = (const float*)d_in[2];
    const float* a   = (const float*)d_in[3];
    float* out = (float*)d_out;

    cudaFuncSetAttribute(k_main, cudaFuncAttributeMaxDynamicSharedMemorySize, SMEMB);

    k_proj <<<1024, 256>>>(h, W, a, adj);      // 512 GEMM CTAs + 512 pack CTAs
    k_main <<<dim3(NN/128, SPLITS, BB), 256, SMEMB>>>();
    k_final<<<(BB*NN*FOUT)/(4*256), 256>>>(out);
}